// round 5
// baseline (speedup 1.0000x reference)
#include <cuda_runtime.h>
#include <math.h>

#define DTF 1e-4f
#define LN_EPS 1e-5f

constexpr int Bb = 16;    // batch
constexpr int S  = 4096;  // sequence
constexpr int D  = 256;   // model dim
constexpr int N  = 16;    // state dim
constexpr int L  = 128;   // chunk length
constexpr int NC = S / L; // 32 chunks per batch

__device__ float g_p[Bb * S * N];        // local prefix states (4 MB)
__device__ float g_carry[Bb * NC * N];   // per-chunk carries

typedef unsigned long long ull;

__device__ __forceinline__ void fma2(ull& d, ull a, ull b) {
    asm("fma.rn.f32x2 %0, %1, %2, %0;" : "+l"(d) : "l"(a), "l"(b));
}
__device__ __forceinline__ ull fma2g(ull a, ull b, ull c) {
    ull d; asm("fma.rn.f32x2 %0, %1, %2, %3;" : "=l"(d) : "l"(a), "l"(b), "l"(c)); return d;
}
__device__ __forceinline__ ull mul2(ull a, ull b) {
    ull d; asm("mul.rn.f32x2 %0, %1, %2;" : "=l"(d) : "l"(a), "l"(b)); return d;
}
__device__ __forceinline__ ull add2(ull a, ull b) {
    ull d; asm("add.rn.f32x2 %0, %1, %2;" : "=l"(d) : "l"(a), "l"(b)); return d;
}
__device__ __forceinline__ ull splat2(float v) {
    ull r; asm("mov.b64 %0, {%1, %1};" : "=l"(r) : "f"(v)); return r;
}
__device__ __forceinline__ float fold2(ull v) {
    float lo, hi; asm("mov.b64 {%0, %1}, %2;" : "=f"(lo), "=f"(hi) : "l"(v));
    return lo + hi;
}

__device__ __forceinline__ float clip10(float v) {
    return fminf(fmaxf(v, -10.0f), 10.0f);
}

// Multi-value warp reduction: 16 accumulators over 32 lanes.
// Result on even lanes; n = (lane>>1)&15.
__device__ __forceinline__ float mv_reduce16(float a[16], int lane) {
    {
        const bool hb = (lane & 16) != 0;
        #pragma unroll
        for (int t = 0; t < 8; t++) {
            float keep = hb ? a[t + 8] : a[t];
            float send = hb ? a[t] : a[t + 8];
            a[t] = keep + __shfl_xor_sync(0xffffffffu, send, 16);
        }
    }
    {
        const bool hb = (lane & 8) != 0;
        #pragma unroll
        for (int t = 0; t < 4; t++) {
            float keep = hb ? a[t + 4] : a[t];
            float send = hb ? a[t] : a[t + 4];
            a[t] = keep + __shfl_xor_sync(0xffffffffu, send, 8);
        }
    }
    {
        const bool hb = (lane & 4) != 0;
        #pragma unroll
        for (int t = 0; t < 2; t++) {
            float keep = hb ? a[t + 2] : a[t];
            float send = hb ? a[t] : a[t + 2];
            a[t] = keep + __shfl_xor_sync(0xffffffffu, send, 4);
        }
    }
    {
        const bool hb = (lane & 2) != 0;
        float keep = hb ? a[1] : a[0];
        float send = hb ? a[0] : a[1];
        a[0] = keep + __shfl_xor_sync(0xffffffffu, send, 2);
    }
    a[0] += __shfl_xor_sync(0xffffffffu, a[0], 1);
    return a[0];
}

// ---------------------------------------------------------------------------
// Kernel A: W = (DT*Bm) @ u with f32x2 FMAs + LDS.128 + x prefetch pipeline,
// then 2-level local scan.
// ---------------------------------------------------------------------------
__global__ void __launch_bounds__(256, 2) kA(const float* __restrict__ x,
                                             const float* __restrict__ A,
                                             const float* __restrict__ Bm) {
    __shared__ ulonglong2 bd4s[64 * 17];   // 17408 B
    __shared__ float Wbuf[L * N];          // 8192 B
    __shared__ float sub[8 * N], pre[8 * N];

    const int c = blockIdx.x, b = blockIdx.y;
    const int tid = threadIdx.x, lane = tid & 31, warp = tid >> 5;

    {
        float* bdf = reinterpret_cast<float*>(bd4s);
        for (int idx = tid; idx < N * D; idx += 256) {
            const int n = idx >> 8, d = idx & 255;     // Bm is [N][D] row-major
            bdf[((d >> 2) * 17 + n) * 4 + (d & 3)] = DTF * Bm[idx];
        }
    }
    __syncthreads();

    const ulonglong2* xw = reinterpret_cast<const ulonglong2*>(
        x + (size_t)(b * S + c * L + warp * 16) * D);   // 16 rows per warp; 64 u2/row

    // Preload first row-pair
    ulonglong2 xv0[2], xv1[2];
    #pragma unroll
    for (int k4 = 0; k4 < 2; k4++) {
        xv0[k4] = xw[lane + 32 * k4];
        xv1[k4] = xw[64 + lane + 32 * k4];
    }

    // ---- Phase 1: row-pair GEMM, packed f32x2, pipelined x loads ----
    #pragma unroll 1
    for (int i = 0; i < 8; i++) {
        // Issue next pair's loads first (overlap with FMA work below)
        ulonglong2 nx0[2], nx1[2];
        if (i < 7) {
            const ulonglong2* xn = xw + (size_t)(i + 1) * 128;
            #pragma unroll
            for (int k4 = 0; k4 < 2; k4++) {
                nx0[k4] = xn[lane + 32 * k4];
                nx1[k4] = xn[64 + lane + 32 * k4];
            }
        }

        ull a0[16], a1[16];
        #pragma unroll
        for (int n = 0; n < 16; n++) { a0[n] = 0ull; a1[n] = 0ull; }

        #pragma unroll
        for (int k4 = 0; k4 < 2; k4++) {
            const int d4 = lane + 32 * k4;
            const ull x0lo = xv0[k4].x, x0hi = xv0[k4].y;
            const ull x1lo = xv1[k4].x, x1hi = xv1[k4].y;
            #pragma unroll
            for (int n = 0; n < 16; n++) {
                const ulonglong2 bv = bd4s[d4 * 17 + n];
                fma2(a0[n], x0lo, bv.x);
                fma2(a0[n], x0hi, bv.y);
                fma2(a1[n], x1lo, bv.x);
                fma2(a1[n], x1hi, bv.y);
            }
        }

        float fa0[16], fa1[16];
        #pragma unroll
        for (int n = 0; n < 16; n++) { fa0[n] = fold2(a0[n]); fa1[n] = fold2(a1[n]); }

        const float r0 = mv_reduce16(fa0, lane);
        const float r1 = mv_reduce16(fa1, lane);
        const int j0 = warp * 16 + i * 2;
        if ((lane & 1) == 0) {
            const int n = (lane >> 1) & 15;
            Wbuf[j0 * 16 + n]       = r0;
            Wbuf[(j0 + 1) * 16 + n] = r1;
        }

        #pragma unroll
        for (int k4 = 0; k4 < 2; k4++) { xv0[k4] = nx0[k4]; xv1[k4] = nx1[k4]; }
    }
    __syncwarp();

    // ---- Level-1 scan: each warp scans its own 16 rows ----
    float Ad = 0.f;
    if (lane < 16) {
        Ad = expf(-DTF * fabsf(A[lane]));
        float p = 0.f;
        #pragma unroll
        for (int r = 0; r < 16; r++) {
            const int j = warp * 16 + r;
            p = fmaf(p, Ad, Wbuf[j * 16 + lane]);
            Wbuf[j * 16 + lane] = p;
        }
        sub[warp * 16 + lane] = p;
    }
    __syncthreads();

    // ---- Level-2 scan + publish chunk aggregate ----
    if (warp == 0 && lane < 16) {
        float AL16 = Ad;
        #pragma unroll
        for (int t = 0; t < 4; t++) AL16 *= AL16;   // Ad^16
        float run = 0.f;
        #pragma unroll
        for (int w = 0; w < 8; w++) {
            pre[w * 16 + lane] = run;
            run = fmaf(run, AL16, sub[w * 16 + lane]);
        }
        g_carry[(b * NC + c) * N + lane] = run;
    }
    __syncthreads();

    // ---- Apply level-2 prefix ----
    if (lane < 16 && warp > 0) {
        const float pref = pre[warp * 16 + lane];
        float f = Ad;
        #pragma unroll
        for (int r = 0; r < 16; r++) {
            const int j = warp * 16 + r;
            Wbuf[j * 16 + lane] = fmaf(f, pref, Wbuf[j * 16 + lane]);
            f *= Ad;
        }
    }
    __syncthreads();

    float4* pg = reinterpret_cast<float4*>(g_p + (size_t)(b * S + c * L) * N);
    const float4* wb = reinterpret_cast<const float4*>(Wbuf);
    for (int idx = tid; idx < L * N / 4; idx += 256) pg[idx] = wb[idx];
}

// ---------------------------------------------------------------------------
// Kernel C: carry prefix + h_t + y = h@Cm^T + u*Dv + LayerNorm, packed f32x2,
// with x/g_p prefetch pipeline. (y-clip provably identity; h-clip kept.)
// ---------------------------------------------------------------------------
__global__ void __launch_bounds__(256, 2) kC(const float* __restrict__ x,
                                             const float* __restrict__ A,
                                             const float* __restrict__ Cm,
                                             const float* __restrict__ Dv,
                                             const float* __restrict__ gamma,
                                             const float* __restrict__ beta,
                                             float* __restrict__ out) {
    __shared__ ulonglong2 cm4s[64 * 17];           // packed Cm^T tiles
    __shared__ ulonglong2 dvs4[64], gs4[64], bs4[64];
    __shared__ float part[31 * N];
    __shared__ float hin_s[N];

    const int c = blockIdx.x, b = blockIdx.y;
    const int tid = threadIdx.x, lane = tid & 31, warp = tid >> 5;

    {
        float* cmf = reinterpret_cast<float*>(cm4s);
        for (int idx = tid; idx < N * D; idx += 256) {
            const int d = idx >> 4, n = idx & 15;      // Cm is [D][N] row-major
            cmf[((d >> 2) * 17 + n) * 4 + (d & 3)] = Cm[idx];
        }
        float* dvf = reinterpret_cast<float*>(dvs4);
        float* gf  = reinterpret_cast<float*>(gs4);
        float* bf  = reinterpret_cast<float*>(bs4);
        if (tid < D) { dvf[tid] = Dv[tid]; gf[tid] = gamma[tid]; bf[tid] = beta[tid]; }
    }

    // ---- Inter-chunk carry: parallel weighted gather of predecessor aggregates ----
    if (c > 0) {
        const int n = tid & 15, cc0 = tid >> 4;
        const float Adn = expf(-DTF * fabsf(A[n]));
        float AL = Adn;
        #pragma unroll
        for (int t = 0; t < 7; t++) AL *= AL;          // Ad^128
        #pragma unroll
        for (int rep = 0; rep < 2; rep++) {
            const int cc = cc0 + rep * 16;
            if (cc < c) {
                int e = c - 1 - cc;
                float wgt = 1.f, base = AL;
                while (e) { if (e & 1) wgt *= base; base *= base; e >>= 1; }
                part[cc * 16 + n] = wgt * g_carry[(b * NC + cc) * N + n];
            }
        }
    }
    __syncthreads();
    if (warp == 0 && lane < 16) {
        float h = 0.f;
        for (int cc = 0; cc < c; cc++) h += part[cc * 16 + lane];
        hin_s[lane] = h;
    }
    __syncthreads();

    const float hin = hin_s[lane & 15];
    const float Ad  = expf(-DTF * fabsf(A[lane & 15]));

    const float Ad2 = Ad * Ad;
    float Ad16 = Ad2;
    Ad16 *= Ad16; Ad16 *= Ad16; Ad16 *= Ad16;          // Ad^16
    float f = Ad;
    for (int w = 0; w < warp; w++) f *= Ad16;          // Ad^(warp*16+1)

    const size_t rowBase = (size_t)(b * S) + c * L + warp * 16;
    const ulonglong2* xw = reinterpret_cast<const ulonglong2*>(x + rowBase * D);
    const float* pw = g_p + rowBase * N;

    // Preload first row-pair (x + p); branch-free lane&15 addressing for p.
    ulonglong2 xv0[2], xv1[2];
    float pv0, pv1;
    #pragma unroll
    for (int k4 = 0; k4 < 2; k4++) {
        xv0[k4] = xw[lane + 32 * k4];
        xv1[k4] = xw[64 + lane + 32 * k4];
    }
    pv0 = pw[lane & 15];
    pv1 = pw[16 + (lane & 15)];

    #pragma unroll 1
    for (int i = 0; i < 8; i++) {
        // Issue next pair's loads first
        ulonglong2 nx0[2], nx1[2];
        float np0 = 0.f, np1 = 0.f;
        if (i < 7) {
            const ulonglong2* xn = xw + (size_t)(i + 1) * 128;
            #pragma unroll
            for (int k4 = 0; k4 < 2; k4++) {
                nx0[k4] = xn[lane + 32 * k4];
                nx1[k4] = xn[64 + lane + 32 * k4];
            }
            np0 = pw[(i + 1) * 32 + (lane & 15)];
            np1 = pw[(i + 1) * 32 + 16 + (lane & 15)];
        }

        const float hn0 = clip10(fmaf(f,      hin, pv0));
        const float hn1 = clip10(fmaf(f * Ad, hin, pv1));
        f *= Ad2;

        ulonglong2 y0[2], y1[2];
        #pragma unroll
        for (int k4 = 0; k4 < 2; k4++) {
            const ulonglong2 dv = dvs4[lane + 32 * k4];
            y0[k4].x = mul2(xv0[k4].x, dv.x);  y0[k4].y = mul2(xv0[k4].y, dv.y);
            y1[k4].x = mul2(xv1[k4].x, dv.x);  y1[k4].y = mul2(xv1[k4].y, dv.y);
        }

        #pragma unroll
        for (int n = 0; n < 16; n++) {
            const ull hp0 = splat2(__shfl_sync(0xffffffffu, hn0, n));
            const ull hp1 = splat2(__shfl_sync(0xffffffffu, hn1, n));
            #pragma unroll
            for (int k4 = 0; k4 < 2; k4++) {
                const ulonglong2 cv = cm4s[(lane + 32 * k4) * 17 + n];
                fma2(y0[k4].x, hp0, cv.x);
                fma2(y0[k4].y, hp0, cv.y);
                fma2(y1[k4].x, hp1, cv.x);
                fma2(y1[k4].y, hp1, cv.y);
            }
        }

        // LayerNorm statistics
        float s0 = fold2(add2(add2(y0[0].x, y0[0].y), add2(y0[1].x, y0[1].y)));
        float s1 = fold2(add2(add2(y1[0].x, y1[0].y), add2(y1[1].x, y1[1].y)));
        ull q0 = 0ull, q1 = 0ull;
        #pragma unroll
        for (int k4 = 0; k4 < 2; k4++) {
            fma2(q0, y0[k4].x, y0[k4].x); fma2(q0, y0[k4].y, y0[k4].y);
            fma2(q1, y1[k4].x, y1[k4].x); fma2(q1, y1[k4].y, y1[k4].y);
        }
        float ss0 = fold2(q0), ss1 = fold2(q1);

        #pragma unroll
        for (int off = 16; off >= 1; off >>= 1) {
            s0  += __shfl_xor_sync(0xffffffffu, s0, off);
            ss0 += __shfl_xor_sync(0xffffffffu, ss0, off);
            s1  += __shfl_xor_sync(0xffffffffu, s1, off);
            ss1 += __shfl_xor_sync(0xffffffffu, ss1, off);
        }
        const float mu0 = s0 * (1.0f / 256.0f);
        const float r0v = rsqrtf(fmaf(ss0, 1.0f / 256.0f, -mu0 * mu0) + LN_EPS);
        const float mu1 = s1 * (1.0f / 256.0f);
        const float r1v = rsqrtf(fmaf(ss1, 1.0f / 256.0f, -mu1 * mu1) + LN_EPS);

        const ull rp0 = splat2(r0v), mp0 = splat2(-mu0 * r0v);
        const ull rp1 = splat2(r1v), mp1 = splat2(-mu1 * r1v);

        const size_t row0 = rowBase + i * 2;
        ulonglong2* o0 = reinterpret_cast<ulonglong2*>(out + row0 * D);
        ulonglong2* o1 = reinterpret_cast<ulonglong2*>(out + (row0 + 1) * D);
        #pragma unroll
        for (int k4 = 0; k4 < 2; k4++) {
            const ulonglong2 g = gs4[lane + 32 * k4];
            const ulonglong2 bb = bs4[lane + 32 * k4];
            ulonglong2 w0, w1;
            w0.x = fma2g(fma2g(y0[k4].x, rp0, mp0), g.x, bb.x);
            w0.y = fma2g(fma2g(y0[k4].y, rp0, mp0), g.y, bb.y);
            w1.x = fma2g(fma2g(y1[k4].x, rp1, mp1), g.x, bb.x);
            w1.y = fma2g(fma2g(y1[k4].y, rp1, mp1), g.y, bb.y);
            o0[lane + 32 * k4] = w0;
            o1[lane + 32 * k4] = w1;
        }

        #pragma unroll
        for (int k4 = 0; k4 < 2; k4++) { xv0[k4] = nx0[k4]; xv1[k4] = nx1[k4]; }
        pv0 = np0; pv1 = np1;
    }
}

extern "C" void kernel_launch(void* const* d_in, const int* in_sizes, int n_in,
                              void* d_out, int out_size) {
    const float* x     = (const float*)d_in[0];
    const float* A     = (const float*)d_in[1];
    const float* Bm    = (const float*)d_in[2];
    const float* Cm    = (const float*)d_in[3];
    const float* Dv    = (const float*)d_in[4];
    const float* gamma = (const float*)d_in[5];
    const float* beta  = (const float*)d_in[6];
    float* out = (float*)d_out;

    kA<<<dim3(NC, Bb), 256>>>(x, A, Bm);
    kC<<<dim3(NC, Bb), 256>>>(x, A, Cm, Dv, gamma, beta, out);
}

// round 6
// speedup vs baseline: 1.4551x; 1.4551x over previous
#include <cuda_runtime.h>
#include <math.h>

#define DTF 1e-4f
#define LN_EPS 1e-5f

constexpr int Bb = 16;    // batch
constexpr int S  = 4096;  // sequence
constexpr int D  = 256;   // model dim
constexpr int N  = 16;    // state dim
constexpr int L  = 128;   // chunk length
constexpr int NC = S / L; // 32 chunks per batch

__device__ float g_p[Bb * S * N];        // local prefix states (4 MB)
__device__ float g_carry[Bb * NC * N];   // per-chunk carries

typedef unsigned long long ull;

__device__ __forceinline__ void fma2(ull& d, ull a, ull b) {
    asm("fma.rn.f32x2 %0, %1, %2, %0;" : "+l"(d) : "l"(a), "l"(b));
}
__device__ __forceinline__ ull fma2g(ull a, ull b, ull c) {
    ull d; asm("fma.rn.f32x2 %0, %1, %2, %3;" : "=l"(d) : "l"(a), "l"(b), "l"(c)); return d;
}
__device__ __forceinline__ ull mul2(ull a, ull b) {
    ull d; asm("mul.rn.f32x2 %0, %1, %2;" : "=l"(d) : "l"(a), "l"(b)); return d;
}
__device__ __forceinline__ ull add2(ull a, ull b) {
    ull d; asm("add.rn.f32x2 %0, %1, %2;" : "=l"(d) : "l"(a), "l"(b)); return d;
}
__device__ __forceinline__ ull splat2(float v) {
    ull r; asm("mov.b64 %0, {%1, %1};" : "=l"(r) : "f"(v)); return r;
}
__device__ __forceinline__ float fold2(ull v) {
    float lo, hi; asm("mov.b64 {%0, %1}, %2;" : "=f"(lo), "=f"(hi) : "l"(v));
    return lo + hi;
}

__device__ __forceinline__ float clip10(float v) {
    return fminf(fmaxf(v, -10.0f), 10.0f);
}

// 32-value butterfly reduction: lane l ends with the full 32-lane sum of v[l].
__device__ __forceinline__ float mv_reduce32(float v[32], int lane) {
    {
        const bool hb = (lane & 16) != 0;
        #pragma unroll
        for (int t = 0; t < 16; t++) {
            float keep = hb ? v[t + 16] : v[t];
            float send = hb ? v[t] : v[t + 16];
            v[t] = keep + __shfl_xor_sync(0xffffffffu, send, 16);
        }
    }
    {
        const bool hb = (lane & 8) != 0;
        #pragma unroll
        for (int t = 0; t < 8; t++) {
            float keep = hb ? v[t + 8] : v[t];
            float send = hb ? v[t] : v[t + 8];
            v[t] = keep + __shfl_xor_sync(0xffffffffu, send, 8);
        }
    }
    {
        const bool hb = (lane & 4) != 0;
        #pragma unroll
        for (int t = 0; t < 4; t++) {
            float keep = hb ? v[t + 4] : v[t];
            float send = hb ? v[t] : v[t + 4];
            v[t] = keep + __shfl_xor_sync(0xffffffffu, send, 4);
        }
    }
    {
        const bool hb = (lane & 2) != 0;
        #pragma unroll
        for (int t = 0; t < 2; t++) {
            float keep = hb ? v[t + 2] : v[t];
            float send = hb ? v[t] : v[t + 2];
            v[t] = keep + __shfl_xor_sync(0xffffffffu, send, 2);
        }
    }
    {
        const bool hb = (lane & 1) != 0;
        float keep = hb ? v[1] : v[0];
        float send = hb ? v[0] : v[1];
        v[0] = keep + __shfl_xor_sync(0xffffffffu, send, 1);
    }
    return v[0];
}

// ---------------------------------------------------------------------------
// Kernel A v2: warp-split GEMM. Warp w: rows [32*(w>>1), +32), n-half (w&1).
// 4-row quads, 8 n per warp: 16 LDS.128 : 128 fma2 per quad; one 32-value
// butterfly per 4 rows. Then 2-level local scan.
// ---------------------------------------------------------------------------
__global__ void __launch_bounds__(256, 2) kA(const float* __restrict__ x,
                                             const float* __restrict__ A,
                                             const float* __restrict__ Bm) {
    __shared__ float bd[N * D];        // identity layout: bd[n*256+d] = DT*Bm[n][d]
    __shared__ float Wbuf[L * N];
    __shared__ float sub[8 * N], pre[8 * N];

    const int c = blockIdx.x, b = blockIdx.y;
    const int tid = threadIdx.x, lane = tid & 31, warp = tid >> 5;
    const int rg = warp >> 1, nh = warp & 1;

    {
        const float4* Bm4 = reinterpret_cast<const float4*>(Bm);
        float4* bd4 = reinterpret_cast<float4*>(bd);
        for (int idx = tid; idx < N * D / 4; idx += 256) {
            float4 v = Bm4[idx];
            v.x *= DTF; v.y *= DTF; v.z *= DTF; v.w *= DTF;
            bd4[idx] = v;
        }
    }
    __syncthreads();

    const ulonglong2* xw = reinterpret_cast<const ulonglong2*>(
        x + (size_t)(b * S + c * L + rg * 32) * D);      // 32 rows; 64 u2/row
    const ulonglong2* bdu = reinterpret_cast<const ulonglong2*>(bd);  // [n*64 + d4]

    #pragma unroll 1
    for (int q = 0; q < 8; q++) {
        // Front-batched loads: 8 LDG.128, MLP=8
        ulonglong2 xv[4][2];
        #pragma unroll
        for (int r = 0; r < 4; r++)
            #pragma unroll
            for (int k4 = 0; k4 < 2; k4++)
                xv[r][k4] = xw[(size_t)(q * 4 + r) * 64 + lane + 32 * k4];

        ull a[4][8];
        #pragma unroll
        for (int r = 0; r < 4; r++)
            #pragma unroll
            for (int n8 = 0; n8 < 8; n8++) a[r][n8] = 0ull;

        #pragma unroll
        for (int k4 = 0; k4 < 2; k4++) {
            const int d4 = lane + 32 * k4;
            #pragma unroll
            for (int n8 = 0; n8 < 8; n8++) {
                const ulonglong2 bv = bdu[(nh * 8 + n8) * 64 + d4];
                #pragma unroll
                for (int r = 0; r < 4; r++) {
                    fma2(a[r][n8], xv[r][k4].x, bv.x);
                    fma2(a[r][n8], xv[r][k4].y, bv.y);
                }
            }
        }

        float fa[32];
        #pragma unroll
        for (int r = 0; r < 4; r++)
            #pragma unroll
            for (int n8 = 0; n8 < 8; n8++) fa[r * 8 + n8] = fold2(a[r][n8]);

        const float res = mv_reduce32(fa, lane);
        // lane l -> (row offset r = l>>3, n8 = l&7)
        Wbuf[(rg * 32 + q * 4 + (lane >> 3)) * 16 + nh * 8 + (lane & 7)] = res;
    }
    __syncthreads();   // rows' n-halves written by two different warps

    // ---- Level-1 scan: each warp scans its own 16 rows ----
    float Ad = 0.f;
    if (lane < 16) {
        Ad = expf(-DTF * fabsf(A[lane]));
        float p = 0.f;
        #pragma unroll
        for (int r = 0; r < 16; r++) {
            const int j = warp * 16 + r;
            p = fmaf(p, Ad, Wbuf[j * 16 + lane]);
            Wbuf[j * 16 + lane] = p;
        }
        sub[warp * 16 + lane] = p;
    }
    __syncthreads();

    // ---- Level-2 scan + publish chunk aggregate ----
    if (warp == 0 && lane < 16) {
        float AL16 = Ad;
        #pragma unroll
        for (int t = 0; t < 4; t++) AL16 *= AL16;   // Ad^16
        float run = 0.f;
        #pragma unroll
        for (int w = 0; w < 8; w++) {
            pre[w * 16 + lane] = run;
            run = fmaf(run, AL16, sub[w * 16 + lane]);
        }
        g_carry[(b * NC + c) * N + lane] = run;
    }
    __syncthreads();

    // ---- Apply level-2 prefix ----
    if (lane < 16 && warp > 0) {
        const float pref = pre[warp * 16 + lane];
        float f = Ad;
        #pragma unroll
        for (int r = 0; r < 16; r++) {
            const int j = warp * 16 + r;
            Wbuf[j * 16 + lane] = fmaf(f, pref, Wbuf[j * 16 + lane]);
            f *= Ad;
        }
    }
    __syncthreads();

    float4* pg = reinterpret_cast<float4*>(g_p + (size_t)(b * S + c * L) * N);
    const float4* wb = reinterpret_cast<const float4*>(Wbuf);
    for (int idx = tid; idx < L * N / 4; idx += 256) pg[idx] = wb[idx];
}

// ---------------------------------------------------------------------------
// Kernel C: carry prefix + h_t + y = h@Cm^T + u*Dv + LayerNorm, packed f32x2,
// with x/g_p prefetch pipeline. (y-clip provably identity; h-clip kept.)
// ---------------------------------------------------------------------------
__global__ void __launch_bounds__(256, 2) kC(const float* __restrict__ x,
                                             const float* __restrict__ A,
                                             const float* __restrict__ Cm,
                                             const float* __restrict__ Dv,
                                             const float* __restrict__ gamma,
                                             const float* __restrict__ beta,
                                             float* __restrict__ out) {
    __shared__ ulonglong2 cm4s[64 * 17];           // packed Cm^T tiles
    __shared__ ulonglong2 dvs4[64], gs4[64], bs4[64];
    __shared__ float part[31 * N];
    __shared__ float hin_s[N];

    const int c = blockIdx.x, b = blockIdx.y;
    const int tid = threadIdx.x, lane = tid & 31, warp = tid >> 5;

    {
        float* cmf = reinterpret_cast<float*>(cm4s);
        for (int idx = tid; idx < N * D; idx += 256) {
            const int d = idx >> 4, n = idx & 15;      // Cm is [D][N] row-major
            cmf[((d >> 2) * 17 + n) * 4 + (d & 3)] = Cm[idx];
        }
        float* dvf = reinterpret_cast<float*>(dvs4);
        float* gf  = reinterpret_cast<float*>(gs4);
        float* bf  = reinterpret_cast<float*>(bs4);
        if (tid < D) { dvf[tid] = Dv[tid]; gf[tid] = gamma[tid]; bf[tid] = beta[tid]; }
    }

    // ---- Inter-chunk carry: parallel weighted gather of predecessor aggregates ----
    if (c > 0) {
        const int n = tid & 15, cc0 = tid >> 4;
        const float Adn = expf(-DTF * fabsf(A[n]));
        float AL = Adn;
        #pragma unroll
        for (int t = 0; t < 7; t++) AL *= AL;          // Ad^128
        #pragma unroll
        for (int rep = 0; rep < 2; rep++) {
            const int cc = cc0 + rep * 16;
            if (cc < c) {
                int e = c - 1 - cc;
                float wgt = 1.f, base = AL;
                while (e) { if (e & 1) wgt *= base; base *= base; e >>= 1; }
                part[cc * 16 + n] = wgt * g_carry[(b * NC + cc) * N + n];
            }
        }
    }
    __syncthreads();
    if (warp == 0 && lane < 16) {
        float h = 0.f;
        for (int cc = 0; cc < c; cc++) h += part[cc * 16 + lane];
        hin_s[lane] = h;
    }
    __syncthreads();

    const float hin = hin_s[lane & 15];
    const float Ad  = expf(-DTF * fabsf(A[lane & 15]));

    const float Ad2 = Ad * Ad;
    float Ad16 = Ad2;
    Ad16 *= Ad16; Ad16 *= Ad16; Ad16 *= Ad16;          // Ad^16
    float f = Ad;
    for (int w = 0; w < warp; w++) f *= Ad16;          // Ad^(warp*16+1)

    const size_t rowBase = (size_t)(b * S) + c * L + warp * 16;
    const ulonglong2* xw = reinterpret_cast<const ulonglong2*>(x + rowBase * D);
    const float* pw = g_p + rowBase * N;

    // Preload first row-pair (x + p)
    ulonglong2 xv0[2], xv1[2];
    float pv0, pv1;
    #pragma unroll
    for (int k4 = 0; k4 < 2; k4++) {
        xv0[k4] = xw[lane + 32 * k4];
        xv1[k4] = xw[64 + lane + 32 * k4];
    }
    pv0 = pw[lane & 15];
    pv1 = pw[16 + (lane & 15)];

    #pragma unroll 1
    for (int i = 0; i < 8; i++) {
        // Issue next pair's loads first
        ulonglong2 nx0[2], nx1[2];
        float np0 = 0.f, np1 = 0.f;
        if (i < 7) {
            const ulonglong2* xn = xw + (size_t)(i + 1) * 128;
            #pragma unroll
            for (int k4 = 0; k4 < 2; k4++) {
                nx0[k4] = xn[lane + 32 * k4];
                nx1[k4] = xn[64 + lane + 32 * k4];
            }
            np0 = pw[(i + 1) * 32 + (lane & 15)];
            np1 = pw[(i + 1) * 32 + 16 + (lane & 15)];
        }

        const float hn0 = clip10(fmaf(f,      hin, pv0));
        const float hn1 = clip10(fmaf(f * Ad, hin, pv1));
        f *= Ad2;

        ulonglong2 y0[2], y1[2];
        #pragma unroll
        for (int k4 = 0; k4 < 2; k4++) {
            const ulonglong2 dv = dvs4[lane + 32 * k4];
            y0[k4].x = mul2(xv0[k4].x, dv.x);  y0[k4].y = mul2(xv0[k4].y, dv.y);
            y1[k4].x = mul2(xv1[k4].x, dv.x);  y1[k4].y = mul2(xv1[k4].y, dv.y);
        }

        #pragma unroll
        for (int n = 0; n < 16; n++) {
            const ull hp0 = splat2(__shfl_sync(0xffffffffu, hn0, n));
            const ull hp1 = splat2(__shfl_sync(0xffffffffu, hn1, n));
            #pragma unroll
            for (int k4 = 0; k4 < 2; k4++) {
                const ulonglong2 cv = cm4s[(lane + 32 * k4) * 17 + n];
                fma2(y0[k4].x, hp0, cv.x);
                fma2(y0[k4].y, hp0, cv.y);
                fma2(y1[k4].x, hp1, cv.x);
                fma2(y1[k4].y, hp1, cv.y);
            }
        }

        // LayerNorm statistics
        float s0 = fold2(add2(add2(y0[0].x, y0[0].y), add2(y0[1].x, y0[1].y)));
        float s1 = fold2(add2(add2(y1[0].x, y1[0].y), add2(y1[1].x, y1[1].y)));
        ull q0 = 0ull, q1 = 0ull;
        #pragma unroll
        for (int k4 = 0; k4 < 2; k4++) {
            fma2(q0, y0[k4].x, y0[k4].x); fma2(q0, y0[k4].y, y0[k4].y);
            fma2(q1, y1[k4].x, y1[k4].x); fma2(q1, y1[k4].y, y1[k4].y);
        }
        float ss0 = fold2(q0), ss1 = fold2(q1);

        #pragma unroll
        for (int off = 16; off >= 1; off >>= 1) {
            s0  += __shfl_xor_sync(0xffffffffu, s0, off);
            ss0 += __shfl_xor_sync(0xffffffffu, ss0, off);
            s1  += __shfl_xor_sync(0xffffffffu, s1, off);
            ss1 += __shfl_xor_sync(0xffffffffu, ss1, off);
        }
        const float mu0 = s0 * (1.0f / 256.0f);
        const float r0v = rsqrtf(fmaf(ss0, 1.0f / 256.0f, -mu0 * mu0) + LN_EPS);
        const float mu1 = s1 * (1.0f / 256.0f);
        const float r1v = rsqrtf(fmaf(ss1, 1.0f / 256.0f, -mu1 * mu1) + LN_EPS);

        const ull rp0 = splat2(r0v), mp0 = splat2(-mu0 * r0v);
        const ull rp1 = splat2(r1v), mp1 = splat2(-mu1 * r1v);

        const size_t row0 = rowBase + i * 2;
        ulonglong2* o0 = reinterpret_cast<ulonglong2*>(out + row0 * D);
        ulonglong2* o1 = reinterpret_cast<ulonglong2*>(out + (row0 + 1) * D);
        #pragma unroll
        for (int k4 = 0; k4 < 2; k4++) {
            const ulonglong2 g = gs4[lane + 32 * k4];
            const ulonglong2 bb = bs4[lane + 32 * k4];
            ulonglong2 w0, w1;
            w0.x = fma2g(fma2g(y0[k4].x, rp0, mp0), g.x, bb.x);
            w0.y = fma2g(fma2g(y0[k4].y, rp0, mp0), g.y, bb.y);
            w1.x = fma2g(fma2g(y1[k4].x, rp1, mp1), g.x, bb.x);
            w1.y = fma2g(fma2g(y1[k4].y, rp1, mp1), g.y, bb.y);
            o0[lane + 32 * k4] = w0;
            o1[lane + 32 * k4] = w1;
        }

        #pragma unroll
        for (int k4 = 0; k4 < 2; k4++) { xv0[k4] = nx0[k4]; xv1[k4] = nx1[k4]; }
        pv0 = np0; pv1 = np1;
    }
}

extern "C" void kernel_launch(void* const* d_in, const int* in_sizes, int n_in,
                              void* d_out, int out_size) {
    const float* x     = (const float*)d_in[0];
    const float* A     = (const float*)d_in[1];
    const float* Bm    = (const float*)d_in[2];
    const float* Cm    = (const float*)d_in[3];
    const float* Dv    = (const float*)d_in[4];
    const float* gamma = (const float*)d_in[5];
    const float* beta  = (const float*)d_in[6];
    float* out = (float*)d_out;

    kA<<<dim3(NC, Bb), 256>>>(x, A, Bm);
    kC<<<dim3(NC, Bb), 256>>>(x, A, Cm, Dv, gamma, beta, out);
}

// round 7
// speedup vs baseline: 1.5569x; 1.0700x over previous
#include <cuda_runtime.h>
#include <math.h>

#define DTF 1e-4f
#define LN_EPS 1e-5f

constexpr int Bb = 16;    // batch
constexpr int S  = 4096;  // sequence
constexpr int D  = 256;   // model dim
constexpr int N  = 16;    // state dim
constexpr int L  = 128;   // chunk length
constexpr int NC = S / L; // 32 chunks per batch

__device__ float g_p[Bb * S * N];        // local prefix states (4 MB)
__device__ float g_carry[Bb * NC * N];   // per-chunk carries

typedef unsigned long long ull;

__device__ __forceinline__ void fma2(ull& d, ull a, ull b) {
    asm("fma.rn.f32x2 %0, %1, %2, %0;" : "+l"(d) : "l"(a), "l"(b));
}
__device__ __forceinline__ ull fma2g(ull a, ull b, ull c) {
    ull d; asm("fma.rn.f32x2 %0, %1, %2, %3;" : "=l"(d) : "l"(a), "l"(b), "l"(c)); return d;
}
__device__ __forceinline__ ull mul2(ull a, ull b) {
    ull d; asm("mul.rn.f32x2 %0, %1, %2;" : "=l"(d) : "l"(a), "l"(b)); return d;
}
__device__ __forceinline__ ull add2(ull a, ull b) {
    ull d; asm("add.rn.f32x2 %0, %1, %2;" : "=l"(d) : "l"(a), "l"(b)); return d;
}
__device__ __forceinline__ ull splat2(float v) {
    ull r; asm("mov.b64 %0, {%1, %1};" : "=l"(r) : "f"(v)); return r;
}
__device__ __forceinline__ float fold2(ull v) {
    float lo, hi; asm("mov.b64 {%0, %1}, %2;" : "=f"(lo), "=f"(hi) : "l"(v));
    return lo + hi;
}

__device__ __forceinline__ float clip10(float v) {
    return fminf(fmaxf(v, -10.0f), 10.0f);
}

// 32-value butterfly reduction: lane l ends with the full 32-lane sum of v[l].
__device__ __forceinline__ float mv_reduce32(float v[32], int lane) {
    {
        const bool hb = (lane & 16) != 0;
        #pragma unroll
        for (int t = 0; t < 16; t++) {
            float keep = hb ? v[t + 16] : v[t];
            float send = hb ? v[t] : v[t + 16];
            v[t] = keep + __shfl_xor_sync(0xffffffffu, send, 16);
        }
    }
    {
        const bool hb = (lane & 8) != 0;
        #pragma unroll
        for (int t = 0; t < 8; t++) {
            float keep = hb ? v[t + 8] : v[t];
            float send = hb ? v[t] : v[t + 8];
            v[t] = keep + __shfl_xor_sync(0xffffffffu, send, 8);
        }
    }
    {
        const bool hb = (lane & 4) != 0;
        #pragma unroll
        for (int t = 0; t < 4; t++) {
            float keep = hb ? v[t + 4] : v[t];
            float send = hb ? v[t] : v[t + 4];
            v[t] = keep + __shfl_xor_sync(0xffffffffu, send, 4);
        }
    }
    {
        const bool hb = (lane & 2) != 0;
        #pragma unroll
        for (int t = 0; t < 2; t++) {
            float keep = hb ? v[t + 2] : v[t];
            float send = hb ? v[t] : v[t + 2];
            v[t] = keep + __shfl_xor_sync(0xffffffffu, send, 2);
        }
    }
    {
        const bool hb = (lane & 1) != 0;
        float keep = hb ? v[1] : v[0];
        float send = hb ? v[0] : v[1];
        v[0] = keep + __shfl_xor_sync(0xffffffffu, send, 1);
    }
    return v[0];
}

// ---------------------------------------------------------------------------
// Kernel A (unchanged from round 6): warp-split GEMM + 2-level local scan.
// ---------------------------------------------------------------------------
__global__ void __launch_bounds__(256, 2) kA(const float* __restrict__ x,
                                             const float* __restrict__ A,
                                             const float* __restrict__ Bm) {
    __shared__ float bd[N * D];        // bd[n*256+d] = DT*Bm[n][d]
    __shared__ float Wbuf[L * N];
    __shared__ float sub[8 * N], pre[8 * N];

    const int c = blockIdx.x, b = blockIdx.y;
    const int tid = threadIdx.x, lane = tid & 31, warp = tid >> 5;
    const int rg = warp >> 1, nh = warp & 1;

    {
        const float4* Bm4 = reinterpret_cast<const float4*>(Bm);
        float4* bd4 = reinterpret_cast<float4*>(bd);
        for (int idx = tid; idx < N * D / 4; idx += 256) {
            float4 v = Bm4[idx];
            v.x *= DTF; v.y *= DTF; v.z *= DTF; v.w *= DTF;
            bd4[idx] = v;
        }
    }
    __syncthreads();

    const ulonglong2* xw = reinterpret_cast<const ulonglong2*>(
        x + (size_t)(b * S + c * L + rg * 32) * D);
    const ulonglong2* bdu = reinterpret_cast<const ulonglong2*>(bd);

    #pragma unroll 1
    for (int q = 0; q < 8; q++) {
        ulonglong2 xv[4][2];
        #pragma unroll
        for (int r = 0; r < 4; r++)
            #pragma unroll
            for (int k4 = 0; k4 < 2; k4++)
                xv[r][k4] = xw[(size_t)(q * 4 + r) * 64 + lane + 32 * k4];

        ull a[4][8];
        #pragma unroll
        for (int r = 0; r < 4; r++)
            #pragma unroll
            for (int n8 = 0; n8 < 8; n8++) a[r][n8] = 0ull;

        #pragma unroll
        for (int k4 = 0; k4 < 2; k4++) {
            const int d4 = lane + 32 * k4;
            #pragma unroll
            for (int n8 = 0; n8 < 8; n8++) {
                const ulonglong2 bv = bdu[(nh * 8 + n8) * 64 + d4];
                #pragma unroll
                for (int r = 0; r < 4; r++) {
                    fma2(a[r][n8], xv[r][k4].x, bv.x);
                    fma2(a[r][n8], xv[r][k4].y, bv.y);
                }
            }
        }

        float fa[32];
        #pragma unroll
        for (int r = 0; r < 4; r++)
            #pragma unroll
            for (int n8 = 0; n8 < 8; n8++) fa[r * 8 + n8] = fold2(a[r][n8]);

        const float res = mv_reduce32(fa, lane);
        Wbuf[(rg * 32 + q * 4 + (lane >> 3)) * 16 + nh * 8 + (lane & 7)] = res;
    }
    __syncthreads();

    float Ad = 0.f;
    if (lane < 16) {
        Ad = expf(-DTF * fabsf(A[lane]));
        float p = 0.f;
        #pragma unroll
        for (int r = 0; r < 16; r++) {
            const int j = warp * 16 + r;
            p = fmaf(p, Ad, Wbuf[j * 16 + lane]);
            Wbuf[j * 16 + lane] = p;
        }
        sub[warp * 16 + lane] = p;
    }
    __syncthreads();

    if (warp == 0 && lane < 16) {
        float AL16 = Ad;
        #pragma unroll
        for (int t = 0; t < 4; t++) AL16 *= AL16;
        float run = 0.f;
        #pragma unroll
        for (int w = 0; w < 8; w++) {
            pre[w * 16 + lane] = run;
            run = fmaf(run, AL16, sub[w * 16 + lane]);
        }
        g_carry[(b * NC + c) * N + lane] = run;
    }
    __syncthreads();

    if (lane < 16 && warp > 0) {
        const float pref = pre[warp * 16 + lane];
        float f = Ad;
        #pragma unroll
        for (int r = 0; r < 16; r++) {
            const int j = warp * 16 + r;
            Wbuf[j * 16 + lane] = fmaf(f, pref, Wbuf[j * 16 + lane]);
            f *= Ad;
        }
    }
    __syncthreads();

    float4* pg = reinterpret_cast<float4*>(g_p + (size_t)(b * S + c * L) * N);
    const float4* wb = reinterpret_cast<const float4*>(Wbuf);
    for (int idx = tid; idx < L * N / 4; idx += 256) pg[idx] = wb[idx];
}

// ---------------------------------------------------------------------------
// Kernel C v2: R=4 row-quad tiling + smem-splatted h broadcast (no shfl in
// the GEMM loop). carry prefix + h_t + y = h@Cm^T + u*Dv + LayerNorm.
// ---------------------------------------------------------------------------
__global__ void __launch_bounds__(256, 2) kC(const float* __restrict__ x,
                                             const float* __restrict__ A,
                                             const float* __restrict__ Cm,
                                             const float* __restrict__ Dv,
                                             const float* __restrict__ gamma,
                                             const float* __restrict__ beta,
                                             float* __restrict__ out) {
    __shared__ ulonglong2 cm4s[64 * 17];           // packed Cm^T (pad 17: conflict-free)
    __shared__ ull hsp[L * N];                     // pre-splatted h states (16 KB)
    __shared__ ulonglong2 dvs4[64], gs4[64], bs4[64];
    __shared__ float part[31 * N];
    __shared__ float hin_s[N];

    const int c = blockIdx.x, b = blockIdx.y;
    const int tid = threadIdx.x, lane = tid & 31, warp = tid >> 5;

    {
        float* cmf = reinterpret_cast<float*>(cm4s);
        for (int idx = tid; idx < N * D; idx += 256) {
            const int d = idx >> 4, n = idx & 15;      // Cm is [D][N] row-major
            cmf[((d >> 2) * 17 + n) * 4 + (d & 3)] = Cm[idx];
        }
        float* dvf = reinterpret_cast<float*>(dvs4);
        float* gf  = reinterpret_cast<float*>(gs4);
        float* bf  = reinterpret_cast<float*>(bs4);
        if (tid < D) { dvf[tid] = Dv[tid]; gf[tid] = gamma[tid]; bf[tid] = beta[tid]; }
    }

    // ---- Inter-chunk carry: parallel weighted gather of predecessor aggregates ----
    if (c > 0) {
        const int n = tid & 15, cc0 = tid >> 4;
        const float Adn = expf(-DTF * fabsf(A[n]));
        float AL = Adn;
        #pragma unroll
        for (int t = 0; t < 7; t++) AL *= AL;          // Ad^128
        #pragma unroll
        for (int rep = 0; rep < 2; rep++) {
            const int cc = cc0 + rep * 16;
            if (cc < c) {
                int e = c - 1 - cc;
                float wgt = 1.f, base = AL;
                while (e) { if (e & 1) wgt *= base; base *= base; e >>= 1; }
                part[cc * 16 + n] = wgt * g_carry[(b * NC + cc) * N + n];
            }
        }
    }
    __syncthreads();
    if (warp == 0 && lane < 16) {
        float h = 0.f;
        for (int cc = 0; cc < c; cc++) h += part[cc * 16 + lane];
        hin_s[lane] = h;
    }
    __syncthreads();

    const float hin = hin_s[lane & 15];
    const float Ad  = expf(-DTF * fabsf(A[lane & 15]));
    const float Ad2 = Ad * Ad;
    const float Ad4 = Ad2 * Ad2;
    float Ad16 = Ad4 * Ad4;  Ad16 *= Ad16;             // Ad^16
    float f = Ad;
    for (int w = 0; w < warp; w++) f *= Ad16;          // Ad^(warp*16+1)

    const size_t rowBase = (size_t)(b * S) + c * L + warp * 16;
    const ulonglong2* xw = reinterpret_cast<const ulonglong2*>(x + rowBase * D);
    const float* pw = g_p + rowBase * N;
    ull* hw = hsp + (size_t)warp * 16 * N;             // this warp's 16 rows

    #pragma unroll 1
    for (int q = 0; q < 4; q++) {
        // ---- Front-batched loads: 16 LDG.128 (x) + 4 scalar LDG (p) ----
        ulonglong2 xv[4][2];
        #pragma unroll
        for (int r = 0; r < 4; r++) {
            #pragma unroll
            for (int h = 0; h < 2; h++)
                xv[r][h] = xw[(size_t)(q * 4 + r) * 64 + h * 32 + lane];
        }
        float pv[4];
        #pragma unroll
        for (int r = 0; r < 4; r++) pv[r] = pw[(q * 4 + r) * 16 + (lane & 15)];

        // ---- Compute h for 4 rows, store splatted to smem ----
        if (lane < 16) {
            float fr = f;
            #pragma unroll
            for (int r = 0; r < 4; r++) {
                const float hn = clip10(fmaf(fr, hin, pv[r]));
                hw[(q * 4 + r) * 16 + lane] = splat2(hn);
                fr *= Ad;
            }
        }
        f *= Ad4;
        __syncwarp();

        // ---- y init: u * Dv ----
        ull y[4][4];
        {
            const ulonglong2 dv0 = dvs4[lane];
            const ulonglong2 dv1 = dvs4[32 + lane];
            #pragma unroll
            for (int r = 0; r < 4; r++) {
                y[r][0] = mul2(xv[r][0].x, dv0.x);
                y[r][1] = mul2(xv[r][0].y, dv0.y);
                y[r][2] = mul2(xv[r][1].x, dv1.x);
                y[r][3] = mul2(xv[r][1].y, dv1.y);
            }
        }

        // ---- GEMM: each cv LDS.128 feeds 4 rows; h via uniform LDS.64 ----
        const ull* hrow = hw + q * 4 * 16;
        #pragma unroll
        for (int n = 0; n < 16; n++) {
            const ulonglong2 cv0 = cm4s[lane * 17 + n];
            const ulonglong2 cv1 = cm4s[(32 + lane) * 17 + n];
            #pragma unroll
            for (int r = 0; r < 4; r++) {
                const ull hp = hrow[r * 16 + n];
                fma2(y[r][0], hp, cv0.x);
                fma2(y[r][1], hp, cv0.y);
                fma2(y[r][2], hp, cv1.x);
                fma2(y[r][3], hp, cv1.y);
            }
        }

        // ---- LayerNorm stats (4 rows interleaved) ----
        float s[4], ss[4];
        #pragma unroll
        for (int r = 0; r < 4; r++) {
            s[r] = fold2(add2(add2(y[r][0], y[r][1]), add2(y[r][2], y[r][3])));
            ull qacc = 0ull;
            #pragma unroll
            for (int k = 0; k < 4; k++) fma2(qacc, y[r][k], y[r][k]);
            ss[r] = fold2(qacc);
        }
        #pragma unroll
        for (int off = 16; off >= 1; off >>= 1) {
            #pragma unroll
            for (int r = 0; r < 4; r++) {
                s[r]  += __shfl_xor_sync(0xffffffffu, s[r], off);
                ss[r] += __shfl_xor_sync(0xffffffffu, ss[r], off);
            }
        }

        // ---- Normalize + store ----
        {
            const ulonglong2 g0 = gs4[lane],      g1 = gs4[32 + lane];
            const ulonglong2 b0 = bs4[lane],      b1 = bs4[32 + lane];
            #pragma unroll
            for (int r = 0; r < 4; r++) {
                const float mu = s[r] * (1.0f / 256.0f);
                const float rv = rsqrtf(fmaf(ss[r], 1.0f / 256.0f, -mu * mu) + LN_EPS);
                const ull rp = splat2(rv), mp = splat2(-mu * rv);

                ulonglong2* o = reinterpret_cast<ulonglong2*>(
                    out + (rowBase + q * 4 + r) * D);
                ulonglong2 w0, w1;
                w0.x = fma2g(fma2g(y[r][0], rp, mp), g0.x, b0.x);
                w0.y = fma2g(fma2g(y[r][1], rp, mp), g0.y, b0.y);
                w1.x = fma2g(fma2g(y[r][2], rp, mp), g1.x, b1.x);
                w1.y = fma2g(fma2g(y[r][3], rp, mp), g1.y, b1.y);
                o[lane]      = w0;
                o[32 + lane] = w1;
            }
        }
    }
}

extern "C" void kernel_launch(void* const* d_in, const int* in_sizes, int n_in,
                              void* d_out, int out_size) {
    const float* x     = (const float*)d_in[0];
    const float* A     = (const float*)d_in[1];
    const float* Bm    = (const float*)d_in[2];
    const float* Cm    = (const float*)d_in[3];
    const float* Dv    = (const float*)d_in[4];
    const float* gamma = (const float*)d_in[5];
    const float* beta  = (const float*)d_in[6];
    float* out = (float*)d_out;

    kA<<<dim3(NC, Bb), 256>>>(x, A, Bm);
    kC<<<dim3(NC, Bb), 256>>>(x, A, Cm, Dv, gamma, beta, out);
}

// round 8
// speedup vs baseline: 1.6099x; 1.0340x over previous
#include <cuda_runtime.h>
#include <math.h>

#define DTF 1e-4f
#define LN_EPS 1e-5f

constexpr int Bb = 16;    // batch
constexpr int S  = 4096;  // sequence
constexpr int D  = 256;   // model dim
constexpr int N  = 16;    // state dim
constexpr int L  = 128;   // chunk length
constexpr int NC = S / L; // 32 chunks per batch

__device__ float g_p[Bb * S * N];        // local prefix states (4 MB)
__device__ float g_carry[Bb * NC * N];   // per-chunk carries

typedef unsigned long long ull;

__device__ __forceinline__ void fma2(ull& d, ull a, ull b) {
    asm("fma.rn.f32x2 %0, %1, %2, %0;" : "+l"(d) : "l"(a), "l"(b));
}
__device__ __forceinline__ ull fma2g(ull a, ull b, ull c) {
    ull d; asm("fma.rn.f32x2 %0, %1, %2, %3;" : "=l"(d) : "l"(a), "l"(b), "l"(c)); return d;
}
__device__ __forceinline__ ull mul2(ull a, ull b) {
    ull d; asm("mul.rn.f32x2 %0, %1, %2;" : "=l"(d) : "l"(a), "l"(b)); return d;
}
__device__ __forceinline__ ull add2(ull a, ull b) {
    ull d; asm("add.rn.f32x2 %0, %1, %2;" : "=l"(d) : "l"(a), "l"(b)); return d;
}
__device__ __forceinline__ ull splat2(float v) {
    ull r; asm("mov.b64 %0, {%1, %1};" : "=l"(r) : "f"(v)); return r;
}
__device__ __forceinline__ float fold2(ull v) {
    float lo, hi; asm("mov.b64 {%0, %1}, %2;" : "=f"(lo), "=f"(hi) : "l"(v));
    return lo + hi;
}

__device__ __forceinline__ float clip10(float v) {
    return fminf(fmaxf(v, -10.0f), 10.0f);
}

// 32-value butterfly reduction: lane l ends with the full 32-lane sum of v[l].
__device__ __forceinline__ float mv_reduce32(float v[32], int lane) {
    {
        const bool hb = (lane & 16) != 0;
        #pragma unroll
        for (int t = 0; t < 16; t++) {
            float keep = hb ? v[t + 16] : v[t];
            float send = hb ? v[t] : v[t + 16];
            v[t] = keep + __shfl_xor_sync(0xffffffffu, send, 16);
        }
    }
    {
        const bool hb = (lane & 8) != 0;
        #pragma unroll
        for (int t = 0; t < 8; t++) {
            float keep = hb ? v[t + 8] : v[t];
            float send = hb ? v[t] : v[t + 8];
            v[t] = keep + __shfl_xor_sync(0xffffffffu, send, 8);
        }
    }
    {
        const bool hb = (lane & 4) != 0;
        #pragma unroll
        for (int t = 0; t < 4; t++) {
            float keep = hb ? v[t + 4] : v[t];
            float send = hb ? v[t] : v[t + 4];
            v[t] = keep + __shfl_xor_sync(0xffffffffu, send, 4);
        }
    }
    {
        const bool hb = (lane & 2) != 0;
        #pragma unroll
        for (int t = 0; t < 2; t++) {
            float keep = hb ? v[t + 2] : v[t];
            float send = hb ? v[t] : v[t + 2];
            v[t] = keep + __shfl_xor_sync(0xffffffffu, send, 2);
        }
    }
    {
        const bool hb = (lane & 1) != 0;
        float keep = hb ? v[1] : v[0];
        float send = hb ? v[0] : v[1];
        v[0] = keep + __shfl_xor_sync(0xffffffffu, send, 1);
    }
    return v[0];
}

// ---------------------------------------------------------------------------
// Kernel A (unchanged): warp-split GEMM + 2-level local scan.
// ---------------------------------------------------------------------------
__global__ void __launch_bounds__(256, 2) kA(const float* __restrict__ x,
                                             const float* __restrict__ A,
                                             const float* __restrict__ Bm) {
    __shared__ float bd[N * D];        // bd[n*256+d] = DT*Bm[n][d]
    __shared__ float Wbuf[L * N];
    __shared__ float sub[8 * N], pre[8 * N];

    const int c = blockIdx.x, b = blockIdx.y;
    const int tid = threadIdx.x, lane = tid & 31, warp = tid >> 5;
    const int rg = warp >> 1, nh = warp & 1;

    {
        const float4* Bm4 = reinterpret_cast<const float4*>(Bm);
        float4* bd4 = reinterpret_cast<float4*>(bd);
        for (int idx = tid; idx < N * D / 4; idx += 256) {
            float4 v = Bm4[idx];
            v.x *= DTF; v.y *= DTF; v.z *= DTF; v.w *= DTF;
            bd4[idx] = v;
        }
    }
    __syncthreads();

    const ulonglong2* xw = reinterpret_cast<const ulonglong2*>(
        x + (size_t)(b * S + c * L + rg * 32) * D);
    const ulonglong2* bdu = reinterpret_cast<const ulonglong2*>(bd);

    #pragma unroll 1
    for (int q = 0; q < 8; q++) {
        ulonglong2 xv[4][2];
        #pragma unroll
        for (int r = 0; r < 4; r++)
            #pragma unroll
            for (int k4 = 0; k4 < 2; k4++)
                xv[r][k4] = xw[(size_t)(q * 4 + r) * 64 + lane + 32 * k4];

        ull a[4][8];
        #pragma unroll
        for (int r = 0; r < 4; r++)
            #pragma unroll
            for (int n8 = 0; n8 < 8; n8++) a[r][n8] = 0ull;

        #pragma unroll
        for (int k4 = 0; k4 < 2; k4++) {
            const int d4 = lane + 32 * k4;
            #pragma unroll
            for (int n8 = 0; n8 < 8; n8++) {
                const ulonglong2 bv = bdu[(nh * 8 + n8) * 64 + d4];
                #pragma unroll
                for (int r = 0; r < 4; r++) {
                    fma2(a[r][n8], xv[r][k4].x, bv.x);
                    fma2(a[r][n8], xv[r][k4].y, bv.y);
                }
            }
        }

        float fa[32];
        #pragma unroll
        for (int r = 0; r < 4; r++)
            #pragma unroll
            for (int n8 = 0; n8 < 8; n8++) fa[r * 8 + n8] = fold2(a[r][n8]);

        const float res = mv_reduce32(fa, lane);
        Wbuf[(rg * 32 + q * 4 + (lane >> 3)) * 16 + nh * 8 + (lane & 7)] = res;
    }
    __syncthreads();

    float Ad = 0.f;
    if (lane < 16) {
        Ad = expf(-DTF * fabsf(A[lane]));
        float p = 0.f;
        #pragma unroll
        for (int r = 0; r < 16; r++) {
            const int j = warp * 16 + r;
            p = fmaf(p, Ad, Wbuf[j * 16 + lane]);
            Wbuf[j * 16 + lane] = p;
        }
        sub[warp * 16 + lane] = p;
    }
    __syncthreads();

    if (warp == 0 && lane < 16) {
        float AL16 = Ad;
        #pragma unroll
        for (int t = 0; t < 4; t++) AL16 *= AL16;
        float run = 0.f;
        #pragma unroll
        for (int w = 0; w < 8; w++) {
            pre[w * 16 + lane] = run;
            run = fmaf(run, AL16, sub[w * 16 + lane]);
        }
        g_carry[(b * NC + c) * N + lane] = run;
    }
    __syncthreads();

    if (lane < 16 && warp > 0) {
        const float pref = pre[warp * 16 + lane];
        float f = Ad;
        #pragma unroll
        for (int r = 0; r < 16; r++) {
            const int j = warp * 16 + r;
            Wbuf[j * 16 + lane] = fmaf(f, pref, Wbuf[j * 16 + lane]);
            f *= Ad;
        }
    }
    __syncthreads();

    float4* pg = reinterpret_cast<float4*>(g_p + (size_t)(b * S + c * L) * N);
    const float4* wb = reinterpret_cast<const float4*>(Wbuf);
    for (int idx = tid; idx < L * N / 4; idx += 256) pg[idx] = wb[idx];
}

// ---------------------------------------------------------------------------
// Kernel C v3: 3 blocks/SM (≤84 regs), R=4 quads, h read as n-pairs via
// uniform LDS.128, x staged in 2-row batches to shrink live registers.
// ---------------------------------------------------------------------------
__global__ void __launch_bounds__(256, 3) kC(const float* __restrict__ x,
                                             const float* __restrict__ A,
                                             const float* __restrict__ Cm,
                                             const float* __restrict__ Dv,
                                             const float* __restrict__ gamma,
                                             const float* __restrict__ beta,
                                             float* __restrict__ out) {
    __shared__ ulonglong2 cm4s[64 * 17];           // packed Cm^T (pad 17)
    __shared__ ull hsp[L * N];                     // splatted h states (16 KB)
    __shared__ ulonglong2 dvs4[64], gs4[64], bs4[64];
    __shared__ float part[31 * N];
    __shared__ float hin_s[N];

    const int c = blockIdx.x, b = blockIdx.y;
    const int tid = threadIdx.x, lane = tid & 31, warp = tid >> 5;

    {
        float* cmf = reinterpret_cast<float*>(cm4s);
        for (int idx = tid; idx < N * D; idx += 256) {
            const int d = idx >> 4, n = idx & 15;      // Cm is [D][N] row-major
            cmf[((d >> 2) * 17 + n) * 4 + (d & 3)] = Cm[idx];
        }
        float* dvf = reinterpret_cast<float*>(dvs4);
        float* gf  = reinterpret_cast<float*>(gs4);
        float* bf  = reinterpret_cast<float*>(bs4);
        if (tid < D) { dvf[tid] = Dv[tid]; gf[tid] = gamma[tid]; bf[tid] = beta[tid]; }
    }

    // ---- Inter-chunk carry ----
    if (c > 0) {
        const int n = tid & 15, cc0 = tid >> 4;
        const float Adn = expf(-DTF * fabsf(A[n]));
        float AL = Adn;
        #pragma unroll
        for (int t = 0; t < 7; t++) AL *= AL;          // Ad^128
        #pragma unroll
        for (int rep = 0; rep < 2; rep++) {
            const int cc = cc0 + rep * 16;
            if (cc < c) {
                int e = c - 1 - cc;
                float wgt = 1.f, base = AL;
                while (e) { if (e & 1) wgt *= base; base *= base; e >>= 1; }
                part[cc * 16 + n] = wgt * g_carry[(b * NC + cc) * N + n];
            }
        }
    }
    __syncthreads();
    if (warp == 0 && lane < 16) {
        float h = 0.f;
        for (int cc = 0; cc < c; cc++) h += part[cc * 16 + lane];
        hin_s[lane] = h;
    }
    __syncthreads();

    const float hin = hin_s[lane & 15];
    const float Ad  = expf(-DTF * fabsf(A[lane & 15]));
    const float Ad2 = Ad * Ad;
    const float Ad4 = Ad2 * Ad2;
    float Ad16 = Ad4 * Ad4;  Ad16 *= Ad16;             // Ad^16
    float f = Ad;
    for (int w = 0; w < warp; w++) f *= Ad16;          // Ad^(warp*16+1)

    const size_t rowBase = (size_t)(b * S) + c * L + warp * 16;
    const ulonglong2* xw = reinterpret_cast<const ulonglong2*>(x + rowBase * D);
    const float* pw = g_p + rowBase * N;
    ull* hw = hsp + (size_t)warp * 16 * N;             // this warp's 16 rows

    #pragma unroll 1
    for (int q = 0; q < 4; q++) {
        // ---- h for 4 rows, splatted into smem ----
        {
            float pv[4];
            #pragma unroll
            for (int r = 0; r < 4; r++) pv[r] = pw[(q * 4 + r) * 16 + (lane & 15)];
            if (lane < 16) {
                float fr = f;
                #pragma unroll
                for (int r = 0; r < 4; r++) {
                    const float hn = clip10(fmaf(fr, hin, pv[r]));
                    hw[(q * 4 + r) * 16 + lane] = splat2(hn);
                    fr *= Ad;
                }
            }
            f *= Ad4;
        }

        // ---- y init: u * Dv, staged in 2-row batches (small live set) ----
        ull y[4][4];
        {
            const ulonglong2 dv0 = dvs4[lane];
            const ulonglong2 dv1 = dvs4[32 + lane];
            #pragma unroll
            for (int rb = 0; rb < 2; rb++) {
                ulonglong2 xa[2], xb[2];
                const size_t base = (size_t)(q * 4 + rb * 2) * 64;
                xa[0] = xw[base + lane];        xa[1] = xw[base + 32 + lane];
                xb[0] = xw[base + 64 + lane];   xb[1] = xw[base + 96 + lane];
                y[rb * 2][0]     = mul2(xa[0].x, dv0.x);
                y[rb * 2][1]     = mul2(xa[0].y, dv0.y);
                y[rb * 2][2]     = mul2(xa[1].x, dv1.x);
                y[rb * 2][3]     = mul2(xa[1].y, dv1.y);
                y[rb * 2 + 1][0] = mul2(xb[0].x, dv0.x);
                y[rb * 2 + 1][1] = mul2(xb[0].y, dv0.y);
                y[rb * 2 + 1][2] = mul2(xb[1].x, dv1.x);
                y[rb * 2 + 1][3] = mul2(xb[1].y, dv1.y);
            }
        }
        __syncwarp();

        // ---- GEMM: n-pairs; cv via LDS.128, h-pair via uniform LDS.128 ----
        const ulonglong2* hrow2 = reinterpret_cast<const ulonglong2*>(hw + q * 4 * 16);
        #pragma unroll
        for (int np = 0; np < 8; np++) {
            const ulonglong2 cv0a = cm4s[lane * 17 + 2 * np];
            const ulonglong2 cv0b = cm4s[lane * 17 + 2 * np + 1];
            const ulonglong2 cv1a = cm4s[(32 + lane) * 17 + 2 * np];
            const ulonglong2 cv1b = cm4s[(32 + lane) * 17 + 2 * np + 1];
            #pragma unroll
            for (int r = 0; r < 4; r++) {
                const ulonglong2 hp = hrow2[r * 8 + np];  // .x=splat h[2np], .y=splat h[2np+1]
                fma2(y[r][0], hp.x, cv0a.x);
                fma2(y[r][1], hp.x, cv0a.y);
                fma2(y[r][2], hp.x, cv1a.x);
                fma2(y[r][3], hp.x, cv1a.y);
                fma2(y[r][0], hp.y, cv0b.x);
                fma2(y[r][1], hp.y, cv0b.y);
                fma2(y[r][2], hp.y, cv1b.x);
                fma2(y[r][3], hp.y, cv1b.y);
            }
        }

        // ---- LayerNorm stats ----
        float s[4], ss[4];
        #pragma unroll
        for (int r = 0; r < 4; r++) {
            s[r] = fold2(add2(add2(y[r][0], y[r][1]), add2(y[r][2], y[r][3])));
            ull qacc = 0ull;
            #pragma unroll
            for (int k = 0; k < 4; k++) fma2(qacc, y[r][k], y[r][k]);
            ss[r] = fold2(qacc);
        }
        #pragma unroll
        for (int off = 16; off >= 1; off >>= 1) {
            #pragma unroll
            for (int r = 0; r < 4; r++) {
                s[r]  += __shfl_xor_sync(0xffffffffu, s[r], off);
                ss[r] += __shfl_xor_sync(0xffffffffu, ss[r], off);
            }
        }

        // ---- Normalize + store ----
        #pragma unroll
        for (int r = 0; r < 4; r++) {
            const float mu = s[r] * (1.0f / 256.0f);
            const float rv = rsqrtf(fmaf(ss[r], 1.0f / 256.0f, -mu * mu) + LN_EPS);
            const ull rp = splat2(rv), mp = splat2(-mu * rv);

            ulonglong2* o = reinterpret_cast<ulonglong2*>(out + (rowBase + q * 4 + r) * D);
            ulonglong2 w0, w1;
            {
                const ulonglong2 g0 = gs4[lane], b0 = bs4[lane];
                w0.x = fma2g(fma2g(y[r][0], rp, mp), g0.x, b0.x);
                w0.y = fma2g(fma2g(y[r][1], rp, mp), g0.y, b0.y);
            }
            {
                const ulonglong2 g1 = gs4[32 + lane], b1 = bs4[32 + lane];
                w1.x = fma2g(fma2g(y[r][2], rp, mp), g1.x, b1.x);
                w1.y = fma2g(fma2g(y[r][3], rp, mp), g1.y, b1.y);
            }
            o[lane]      = w0;
            o[32 + lane] = w1;
        }
    }
}

extern "C" void kernel_launch(void* const* d_in, const int* in_sizes, int n_in,
                              void* d_out, int out_size) {
    const float* x     = (const float*)d_in[0];
    const float* A     = (const float*)d_in[1];
    const float* Bm    = (const float*)d_in[2];
    const float* Cm    = (const float*)d_in[3];
    const float* Dv    = (const float*)d_in[4];
    const float* gamma = (const float*)d_in[5];
    const float* beta  = (const float*)d_in[6];
    float* out = (float*)d_out;

    kA<<<dim3(NC, Bb), 256>>>(x, A, Bm);
    kC<<<dim3(NC, Bb), 256>>>(x, A, Cm, Dv, gamma, beta, out);
}